// round 4
// baseline (speedup 1.0000x reference)
#include <cuda_runtime.h>
#include <math.h>
#include <stdint.h>

#define HDIM   256
#define F0DIM  512
#define CDIM   64
#define MAXN   50000
#define MAXE   800000

// -------- static device scratch (no allocations allowed) --------
__device__ float g_Aa[(size_t)MAXN * HDIM];
__device__ float g_Ab[(size_t)MAXN * HDIM];
__device__ float g_Ba[(size_t)MAXN * HDIM];
__device__ float g_Bb[(size_t)MAXN * HDIM];
__device__ float g_CAT[(size_t)MAXN * 2 * HDIM];

__device__ int   g_counts[MAXN];
__device__ int   g_cursor[MAXN];
__device__ int   g_rowptr[MAXN + 1];
__device__ int   g_csr_src[MAXE];
__device__ float g_csr_w[MAXE];

// ============================================================================
// Tensor-core GEMM, mma.sync m16n8k8 tf32 with 3xTF32 compensation.
// hi/lo split done ONCE at SMEM store; SMEM holds interleaved {hi,lo} pairs.
// 128x128 tile, BK=32, 256 thr (8 warps 2x4), 2-stage SMEM double buffer.
// ============================================================================
#define BM 128
#define BN 128
#define BKK 32
#define SA_STRIDE (2 * BM + 8)          // words per k-row (hi/lo interleaved)
#define SB_STRIDE (2 * BN + 8)
#define SA_WORDS (BKK * SA_STRIDE)
#define SB_WORDS (BKK * SB_STRIDE)
#define SMEM_WORDS (2 * (SA_WORDS + SB_WORDS))

__device__ __forceinline__ uint32_t f2tf32(float x) {
    uint32_t u;
    asm("cvt.rna.tf32.f32 %0, %1;" : "=r"(u) : "f"(x));
    return u;
}
__device__ __forceinline__ float2 split2(float f) {
    uint32_t hi = f2tf32(f);
    uint32_t lo = f2tf32(f - __uint_as_float(hi));
    return make_float2(__uint_as_float(hi), __uint_as_float(lo));
}

__device__ __forceinline__ void mma_tf32(float c[4], const uint32_t a[4], const uint32_t b[2]) {
    asm volatile(
        "mma.sync.aligned.m16n8k8.row.col.f32.tf32.tf32.f32 "
        "{%0,%1,%2,%3}, {%4,%5,%6,%7}, {%8,%9}, {%0,%1,%2,%3};"
        : "+f"(c[0]), "+f"(c[1]), "+f"(c[2]), "+f"(c[3])
        : "r"(a[0]), "r"(a[1]), "r"(a[2]), "r"(a[3]), "r"(b[0]), "r"(b[1]));
}

__global__ void __launch_bounds__(256)
gemm_tc_kernel(const float* __restrict__ A, const float* __restrict__ B,
               const float* __restrict__ bias, float* __restrict__ C,
               int M, int N, int K)
{
    extern __shared__ float smem[];
    float* sAbuf[2] = { smem, smem + SA_WORDS + SB_WORDS };
    float* sBbuf[2] = { smem + SA_WORDS, smem + 2 * SA_WORDS + SB_WORDS };

    const int tid  = threadIdx.x;
    const int warp = tid >> 5;
    const int lane = tid & 31;
    const int g    = lane >> 2;
    const int tig  = lane & 3;
    const int mBase = (warp & 1) * 64;
    const int nBase = (warp >> 1) * 32;
    const int rowBase = blockIdx.y * BM;
    const int colBase = blockIdx.x * BN;

    float acc[4][4][4];
#pragma unroll
    for (int i = 0; i < 4; i++)
#pragma unroll
        for (int j = 0; j < 4; j++)
#pragma unroll
            for (int r = 0; r < 4; r++) acc[i][j][r] = 0.f;

    // global-load indexing
    const int ar     = tid >> 1;           // A row 0..127
    const int ak0    = (tid & 1) * 16;     // A k offset 0 or 16
    const int br     = tid >> 3;           // B k-row 0..31
    const int bcBase = (tid & 7) * 4;      // B col base; +32j strides

    float4 pa[4], pb[4];

    auto loadG = [&](int k0) {
        const int grow = rowBase + ar;
        if (grow < M) {
            const float* ap = A + (size_t)grow * K + k0 + ak0;
#pragma unroll
            for (int j = 0; j < 4; j++) pa[j] = *(const float4*)(ap + j * 4);
        } else {
#pragma unroll
            for (int j = 0; j < 4; j++) pa[j] = make_float4(0.f, 0.f, 0.f, 0.f);
        }
        const float* bp = B + (size_t)(k0 + br) * N + colBase + bcBase;
#pragma unroll
        for (int j = 0; j < 4; j++) {
            int gcol = colBase + bcBase + 32 * j;
            pb[j] = (gcol < N) ? *(const float4*)(bp + 32 * j)
                               : make_float4(0.f, 0.f, 0.f, 0.f);
        }
    };
    auto storeS = [&](int buf) {
        float* sA = sAbuf[buf];
        float* sB = sBbuf[buf];
#pragma unroll
        for (int j = 0; j < 4; j++) {
            const float f[4] = { pa[j].x, pa[j].y, pa[j].z, pa[j].w };
#pragma unroll
            for (int c = 0; c < 4; c++) {
                int k = ak0 + 4 * j + c;
                *(float2*)&sA[k * SA_STRIDE + 2 * ar] = split2(f[c]);
            }
            const float h[4] = { pb[j].x, pb[j].y, pb[j].z, pb[j].w };
#pragma unroll
            for (int c = 0; c < 4; c++) {
                int col = bcBase + 32 * j + c;
                *(float2*)&sB[br * SB_STRIDE + 2 * col] = split2(h[c]);
            }
        }
    };

    loadG(0);
    storeS(0);
    __syncthreads();

    const int nIter = K / BKK;
    for (int it = 0; it < nIter; it++) {
        const bool has_next = (it + 1) < nIter;
        if (has_next) loadG((it + 1) * BKK);

        const float* sA = sAbuf[it & 1];
        const float* sB = sBbuf[it & 1];

#pragma unroll
        for (int ks = 0; ks < 4; ks++) {
            const int k1 = ks * 8 + tig;
            const int k2 = k1 + 4;

            uint32_t ahi[4][4], alo[4][4];
#pragma unroll
            for (int mi = 0; mi < 4; mi++) {
                const int m0 = mBase + mi * 16 + g;
                float2 v0 = *(const float2*)&sA[k1 * SA_STRIDE + 2 * m0];
                float2 v1 = *(const float2*)&sA[k1 * SA_STRIDE + 2 * (m0 + 8)];
                float2 v2 = *(const float2*)&sA[k2 * SA_STRIDE + 2 * m0];
                float2 v3 = *(const float2*)&sA[k2 * SA_STRIDE + 2 * (m0 + 8)];
                ahi[mi][0] = __float_as_uint(v0.x); alo[mi][0] = __float_as_uint(v0.y);
                ahi[mi][1] = __float_as_uint(v1.x); alo[mi][1] = __float_as_uint(v1.y);
                ahi[mi][2] = __float_as_uint(v2.x); alo[mi][2] = __float_as_uint(v2.y);
                ahi[mi][3] = __float_as_uint(v3.x); alo[mi][3] = __float_as_uint(v3.y);
            }
            uint32_t bhi[4][2], blo[4][2];
#pragma unroll
            for (int ni = 0; ni < 4; ni++) {
                const int n0 = nBase + ni * 8 + g;
                float2 u0 = *(const float2*)&sB[k1 * SB_STRIDE + 2 * n0];
                float2 u1 = *(const float2*)&sB[k2 * SB_STRIDE + 2 * n0];
                bhi[ni][0] = __float_as_uint(u0.x); blo[ni][0] = __float_as_uint(u0.y);
                bhi[ni][1] = __float_as_uint(u1.x); blo[ni][1] = __float_as_uint(u1.y);
            }
#pragma unroll
            for (int mi = 0; mi < 4; mi++)
#pragma unroll
                for (int ni = 0; ni < 4; ni++) {
                    mma_tf32(acc[mi][ni], alo[mi], bhi[ni]);
                    mma_tf32(acc[mi][ni], ahi[mi], blo[ni]);
                    mma_tf32(acc[mi][ni], ahi[mi], bhi[ni]);
                }
        }

        if (has_next) storeS((it + 1) & 1);
        __syncthreads();
    }

    // epilogue
#pragma unroll
    for (int mi = 0; mi < 4; mi++) {
#pragma unroll
        for (int ni = 0; ni < 4; ni++) {
            const int col = colBase + nBase + ni * 8 + 2 * tig;
            if (col >= N) continue;
            float bx = 0.f, by = 0.f;
            if (bias) { bx = __ldg(&bias[col]); by = __ldg(&bias[col + 1]); }
            const int row0 = rowBase + mBase + mi * 16 + g;
            const int row1 = row0 + 8;
            if (row0 < M) {
                float2 v = make_float2(acc[mi][ni][0] + bx, acc[mi][ni][1] + by);
                *(float2*)(C + (size_t)row0 * N + col) = v;
            }
            if (row1 < M) {
                float2 v = make_float2(acc[mi][ni][2] + bx, acc[mi][ni][3] + by);
                *(float2*)(C + (size_t)row1 * N + col) = v;
            }
        }
    }
}

// ============================================================================
// CSR build: histogram -> scan -> scatter
// ============================================================================
__global__ void count_kernel(const int* __restrict__ dst, int* __restrict__ counts, int E)
{
    int e = blockIdx.x * blockDim.x + threadIdx.x;
    if (e < E) atomicAdd(&counts[dst[e]], 1);
}

__global__ void __launch_bounds__(1024)
scan_kernel(const int* __restrict__ counts, int* __restrict__ rowptr, int n)
{
    __shared__ int sm[1024];
    __shared__ int carry_s;
    int tid = threadIdx.x;
    if (tid == 0) carry_s = 0;
    __syncthreads();
    for (int base = 0; base < n; base += 1024) {
        int v = (base + tid < n) ? counts[base + tid] : 0;
        sm[tid] = v;
        __syncthreads();
#pragma unroll
        for (int off = 1; off < 1024; off <<= 1) {
            int t = (tid >= off) ? sm[tid - off] : 0;
            __syncthreads();
            sm[tid] += t;
            __syncthreads();
        }
        int carry = carry_s;
        if (base + tid < n) rowptr[base + tid] = carry + sm[tid] - v;
        __syncthreads();
        if (tid == 1023) carry_s = carry + sm[1023];
        __syncthreads();
    }
    if (tid == 0) rowptr[n] = carry_s;
}

__global__ void scatter_kernel(const int* __restrict__ src, const int* __restrict__ dst,
                               const float* __restrict__ w,
                               const int* __restrict__ rowptr, int* __restrict__ cursor,
                               int* __restrict__ csr_src, float* __restrict__ csr_w, int E)
{
    int e = blockIdx.x * blockDim.x + threadIdx.x;
    if (e >= E) return;
    int d = dst[e];
    int pos = rowptr[d] + atomicAdd(&cursor[d], 1);
    csr_src[pos] = src[e];
    csr_w[pos]   = w[e];
}

// ============================================================================
// Gather SpMM, both branches fused, bias(+relu) fused.
// ============================================================================
__global__ void __launch_bounds__(256)
spmm_csr_dual_kernel(const int* __restrict__ rowptr,
                     const int* __restrict__ csr_src, const float* __restrict__ csr_w,
                     const float* __restrict__ ha, const float* __restrict__ hb,
                     float* __restrict__ oa, float* __restrict__ ob,
                     const float* __restrict__ bias_a, const float* __restrict__ bias_b,
                     int Nn, int do_relu)
{
    int node = blockIdx.x * 4 + (threadIdx.x >> 6);
    int c    = threadIdx.x & 63;
    if (node >= Nn) return;

    const float4* ha4 = (const float4*)ha;
    const float4* hb4 = (const float4*)hb;

    float4 acca = make_float4(0.f, 0.f, 0.f, 0.f);
    float4 accb = make_float4(0.f, 0.f, 0.f, 0.f);

    int beg = __ldg(&rowptr[node]);
    int end = __ldg(&rowptr[node + 1]);
    for (int i = beg; i < end; i++) {
        int   s = __ldg(&csr_src[i]);
        float w = __ldg(&csr_w[i]);
        float4 va = __ldg(&ha4[(size_t)s * 64 + c]);
        float4 vb = __ldg(&hb4[(size_t)s * 64 + c]);
        acca.x = fmaf(w, va.x, acca.x); acca.y = fmaf(w, va.y, acca.y);
        acca.z = fmaf(w, va.z, acca.z); acca.w = fmaf(w, va.w, acca.w);
        accb.x = fmaf(w, vb.x, accb.x); accb.y = fmaf(w, vb.y, accb.y);
        accb.z = fmaf(w, vb.z, accb.z); accb.w = fmaf(w, vb.w, accb.w);
    }

    float4 ba = __ldg(&((const float4*)bias_a)[c]);
    float4 bb = __ldg(&((const float4*)bias_b)[c]);
    acca.x += ba.x; acca.y += ba.y; acca.z += ba.z; acca.w += ba.w;
    accb.x += bb.x; accb.y += bb.y; accb.z += bb.z; accb.w += bb.w;
    if (do_relu) {
        acca.x = fmaxf(acca.x, 0.f); acca.y = fmaxf(acca.y, 0.f);
        acca.z = fmaxf(acca.z, 0.f); acca.w = fmaxf(acca.w, 0.f);
        accb.x = fmaxf(accb.x, 0.f); accb.y = fmaxf(accb.y, 0.f);
        accb.z = fmaxf(accb.z, 0.f); accb.w = fmaxf(accb.w, 0.f);
    }
    ((float4*)oa)[(size_t)node * 64 + c] = acca;
    ((float4*)ob)[(size_t)node * 64 + c] = accb;
}

// ============================================================================
// row-wise log_softmax, one warp per row; strided output
// ============================================================================
template <int L>
__global__ void logsoftmax_kernel(const float* __restrict__ in, float* __restrict__ out,
                                  int nrows, int out_stride)
{
    int row  = blockIdx.x * (blockDim.x >> 5) + (threadIdx.x >> 5);
    int lane = threadIdx.x & 31;
    if (row >= nrows) return;
    const float* r = in + (size_t)row * L;
    float vals[L / 32];
    float m = -3.4e38f;
#pragma unroll
    for (int t = 0; t < L / 32; t++) {
        vals[t] = r[lane + t * 32];
        m = fmaxf(m, vals[t]);
    }
#pragma unroll
    for (int o = 16; o; o >>= 1) m = fmaxf(m, __shfl_xor_sync(0xffffffffu, m, o));
    float s = 0.f;
#pragma unroll
    for (int t = 0; t < L / 32; t++) s += expf(vals[t] - m);
#pragma unroll
    for (int o = 16; o; o >>= 1) s += __shfl_xor_sync(0xffffffffu, s, o);
    float lse = m + logf(s);
    float* wptr = out + (size_t)row * out_stride;
#pragma unroll
    for (int t = 0; t < L / 32; t++) wptr[lane + t * 32] = vals[t] - lse;
}

// ============================================================================
// host side
// ============================================================================
static void sgemm(const float* A, const float* B, const float* bias, float* C,
                  int M, int N, int K)
{
    dim3 grid((N + BN - 1) / BN, (M + BM - 1) / BM);
    gemm_tc_kernel<<<grid, 256, SMEM_WORDS * sizeof(float)>>>(A, B, bias, C, M, N, K);
}

extern "C" void kernel_launch(void* const* d_in, const int* in_sizes, int n_in,
                              void* d_out, int out_size)
{
    const float* x0   = (const float*)d_in[0];
    const float* x1   = (const float*)d_in[1];
    const int*   esrc = (const int*)d_in[2];
    const int*   edst = (const int*)d_in[3];
    const float* ew   = (const float*)d_in[4];
    const float* W1a = (const float*)d_in[5];  const float* b1a = (const float*)d_in[6];
    const float* W2a = (const float*)d_in[7];  const float* b2a = (const float*)d_in[8];
    const float* LWa = (const float*)d_in[9];  const float* Lba = (const float*)d_in[10];
    const float* W1b = (const float*)d_in[11]; const float* b1b = (const float*)d_in[12];
    const float* W2b = (const float*)d_in[13]; const float* b2b = (const float*)d_in[14];
    const float* LWb = (const float*)d_in[15]; const float* Lbb = (const float*)d_in[16];
    const float* LW  = (const float*)d_in[17]; const float* Lb  = (const float*)d_in[18];

    const int Nn = in_sizes[0] / F0DIM;
    const int E  = in_sizes[2];

    static bool attr_done = false;
    if (!attr_done) {
        cudaFuncSetAttribute(gemm_tc_kernel,
                             cudaFuncAttributeMaxDynamicSharedMemorySize,
                             SMEM_WORDS * sizeof(float));
        attr_done = true;
    }

    float *Aa, *Ab, *Ba, *Bb, *CAT;
    cudaGetSymbolAddress((void**)&Aa,  g_Aa);
    cudaGetSymbolAddress((void**)&Ab,  g_Ab);
    cudaGetSymbolAddress((void**)&Ba,  g_Ba);
    cudaGetSymbolAddress((void**)&Bb,  g_Bb);
    cudaGetSymbolAddress((void**)&CAT, g_CAT);

    int *counts, *cursor, *rowptr, *csr_src;
    float *csr_w;
    cudaGetSymbolAddress((void**)&counts,  g_counts);
    cudaGetSymbolAddress((void**)&cursor,  g_cursor);
    cudaGetSymbolAddress((void**)&rowptr,  g_rowptr);
    cudaGetSymbolAddress((void**)&csr_src, g_csr_src);
    cudaGetSymbolAddress((void**)&csr_w,   g_csr_w);

    // ---- build CSR by dst ----
    cudaMemsetAsync(counts, 0, Nn * sizeof(int), 0);
    cudaMemsetAsync(cursor, 0, Nn * sizeof(int), 0);
    count_kernel<<<(E + 255) / 256, 256>>>(edst, counts, E);
    scan_kernel<<<1, 1024>>>(counts, rowptr, Nn);
    scatter_kernel<<<(E + 255) / 256, 256>>>(esrc, edst, ew, rowptr, cursor,
                                             csr_src, csr_w, E);

    const int spmmGrid = (Nn + 3) / 4;

    // ---- layer 1 ----
    sgemm(x0, W1a, nullptr, Aa, Nn, HDIM, F0DIM);
    sgemm(x1, W1b, nullptr, Ab, Nn, HDIM, F0DIM);
    spmm_csr_dual_kernel<<<spmmGrid, 256>>>(rowptr, csr_src, csr_w,
                                            Aa, Ab, Ba, Bb, b1a, b1b, Nn, 1);
    // ---- layer 2 ----
    sgemm(Ba, W2a, nullptr, Aa, Nn, HDIM, HDIM);
    sgemm(Bb, W2b, nullptr, Ab, Nn, HDIM, HDIM);
    spmm_csr_dual_kernel<<<spmmGrid, 256>>>(rowptr, csr_src, csr_w,
                                            Aa, Ab, Ba, Bb, b2a, b2b, Nn, 0);
    // ---- branch heads: linear + log_softmax directly into CAT ----
    sgemm(Ba, LWa, Lba, Aa, Nn, HDIM, HDIM);
    sgemm(Bb, LWb, Lbb, Ab, Nn, HDIM, HDIM);
    logsoftmax_kernel<HDIM><<<(Nn + 7) / 8, 256>>>(Aa, CAT,        Nn, 2 * HDIM);
    logsoftmax_kernel<HDIM><<<(Nn + 7) / 8, 256>>>(Ab, CAT + HDIM, Nn, 2 * HDIM);

    // ---- final: out = log_softmax(CAT @ LW + Lb) ----
    sgemm(CAT, LW, Lb, Aa, Nn, CDIM, 2 * HDIM);
    logsoftmax_kernel<CDIM><<<(Nn + 7) / 8, 256>>>(Aa, (float*)d_out, Nn, CDIM);
}

// round 5
// speedup vs baseline: 1.3181x; 1.3181x over previous
#include <cuda_runtime.h>
#include <math.h>
#include <stdint.h>

#define HDIM   256
#define F0DIM  512
#define CDIM   64
#define MAXN   50000
#define MAXE   800000

// -------- static device scratch (no allocations allowed) --------
__device__ float g_Aa[(size_t)MAXN * HDIM];
__device__ float g_Ab[(size_t)MAXN * HDIM];
__device__ float g_Ba[(size_t)MAXN * HDIM];
__device__ float g_Bb[(size_t)MAXN * HDIM];
__device__ float g_CAT[(size_t)MAXN * 2 * HDIM];

__device__ int   g_counts[MAXN];
__device__ int   g_cursor[MAXN];
__device__ int   g_rowptr[MAXN + 1];
__device__ int   g_csr_src[MAXE];
__device__ float g_csr_w[MAXE];

// ============================================================================
// Tensor-core GEMM, mma.sync m16n8k8 tf32 with 3xTF32 compensation.
// hi/lo split done ONCE at SMEM store into 4 SEPARATE planes with R3's
// proven conflict-free [k][m] stride-136 layout. 128x128 tile, BK=32,
// 256 thr (8 warps 2x4), warp tile 64x32, single-buffered SMEM.
// ============================================================================
#define BM 128
#define BN 128
#define BKK 32
#define SA_STRIDE (BM + 8)
#define SB_STRIDE (BN + 8)
#define SA_WORDS (BKK * SA_STRIDE)
#define SB_WORDS (BKK * SB_STRIDE)
#define SMEM_WORDS (2 * SA_WORDS + 2 * SB_WORDS)

__device__ __forceinline__ uint32_t f2tf32(float x) {
    uint32_t u;
    asm("cvt.rna.tf32.f32 %0, %1;" : "=r"(u) : "f"(x));
    return u;
}
__device__ __forceinline__ float2 split2(float f) {
    uint32_t hi = f2tf32(f);
    uint32_t lo = f2tf32(f - __uint_as_float(hi));
    return make_float2(__uint_as_float(hi), __uint_as_float(lo));
}

__device__ __forceinline__ void mma_tf32(float c[4], const uint32_t a[4], const uint32_t b[2]) {
    asm volatile(
        "mma.sync.aligned.m16n8k8.row.col.f32.tf32.tf32.f32 "
        "{%0,%1,%2,%3}, {%4,%5,%6,%7}, {%8,%9}, {%0,%1,%2,%3};"
        : "+f"(c[0]), "+f"(c[1]), "+f"(c[2]), "+f"(c[3])
        : "r"(a[0]), "r"(a[1]), "r"(a[2]), "r"(a[3]), "r"(b[0]), "r"(b[1]));
}

__global__ void __launch_bounds__(256)
gemm_tc_kernel(const float* __restrict__ A, const float* __restrict__ B,
               const float* __restrict__ bias, float* __restrict__ C,
               int M, int N, int K)
{
    extern __shared__ float smem[];
    float* sAhi = smem;                          // [BKK][SA_STRIDE]
    float* sAlo = sAhi + SA_WORDS;
    float* sBhi = sAlo + SA_WORDS;               // [BKK][SB_STRIDE]
    float* sBlo = sBhi + SB_WORDS;

    const int tid  = threadIdx.x;
    const int warp = tid >> 5;
    const int lane = tid & 31;
    const int g    = lane >> 2;
    const int tig  = lane & 3;
    const int mBase = (warp & 1) * 64;
    const int nBase = (warp >> 1) * 32;
    const int rowBase = blockIdx.y * BM;
    const int colBase = blockIdx.x * BN;

    float acc[4][4][4];
#pragma unroll
    for (int i = 0; i < 4; i++)
#pragma unroll
        for (int j = 0; j < 4; j++)
#pragma unroll
            for (int r = 0; r < 4; r++) acc[i][j][r] = 0.f;

    // global-load indexing
    const int ar     = tid >> 1;           // A row 0..127
    const int ak0    = (tid & 1) * 16;     // A k offset 0 or 16
    const int br     = tid >> 3;           // B k-row 0..31
    const int bcBase = (tid & 7) * 4;      // B col base; +32j strides (coalesced)

    float4 pa[4], pb[4];

    auto loadG = [&](int k0) {
        const int grow = rowBase + ar;
        if (grow < M) {
            const float* ap = A + (size_t)grow * K + k0 + ak0;
#pragma unroll
            for (int j = 0; j < 4; j++) pa[j] = *(const float4*)(ap + j * 4);
        } else {
#pragma unroll
            for (int j = 0; j < 4; j++) pa[j] = make_float4(0.f, 0.f, 0.f, 0.f);
        }
        const float* bp = B + (size_t)(k0 + br) * N + colBase + bcBase;
#pragma unroll
        for (int j = 0; j < 4; j++) {
            int gcol = colBase + bcBase + 32 * j;
            pb[j] = (gcol < N) ? *(const float4*)(bp + 32 * j)
                               : make_float4(0.f, 0.f, 0.f, 0.f);
        }
    };
    auto storeS = [&]() {
#pragma unroll
        for (int j = 0; j < 4; j++) {
            const float f[4] = { pa[j].x, pa[j].y, pa[j].z, pa[j].w };
#pragma unroll
            for (int c = 0; c < 4; c++) {
                int k = ak0 + 4 * j + c;
                float2 s = split2(f[c]);
                sAhi[k * SA_STRIDE + ar] = s.x;
                sAlo[k * SA_STRIDE + ar] = s.y;
            }
            const float h[4] = { pb[j].x, pb[j].y, pb[j].z, pb[j].w };
#pragma unroll
            for (int c = 0; c < 4; c++) {
                int col = bcBase + 32 * j + c;
                float2 s = split2(h[c]);
                sBhi[br * SB_STRIDE + col] = s.x;
                sBlo[br * SB_STRIDE + col] = s.y;
            }
        }
    };

    loadG(0);
    storeS();
    __syncthreads();

    const int nIter = K / BKK;
    for (int it = 0; it < nIter; it++) {
        const bool has_next = (it + 1) < nIter;
        if (has_next) loadG((it + 1) * BKK);

#pragma unroll
        for (int ks = 0; ks < 4; ks++) {
            const int k1 = ks * 8 + tig;
            const int k2 = k1 + 4;

            uint32_t ahi[4][4], alo[4][4];
#pragma unroll
            for (int mi = 0; mi < 4; mi++) {
                const int m0 = mBase + mi * 16 + g;
                ahi[mi][0] = __float_as_uint(sAhi[k1 * SA_STRIDE + m0]);
                ahi[mi][1] = __float_as_uint(sAhi[k1 * SA_STRIDE + m0 + 8]);
                ahi[mi][2] = __float_as_uint(sAhi[k2 * SA_STRIDE + m0]);
                ahi[mi][3] = __float_as_uint(sAhi[k2 * SA_STRIDE + m0 + 8]);
                alo[mi][0] = __float_as_uint(sAlo[k1 * SA_STRIDE + m0]);
                alo[mi][1] = __float_as_uint(sAlo[k1 * SA_STRIDE + m0 + 8]);
                alo[mi][2] = __float_as_uint(sAlo[k2 * SA_STRIDE + m0]);
                alo[mi][3] = __float_as_uint(sAlo[k2 * SA_STRIDE + m0 + 8]);
            }
            uint32_t bhi[4][2], blo[4][2];
#pragma unroll
            for (int ni = 0; ni < 4; ni++) {
                const int n0 = nBase + ni * 8 + g;
                bhi[ni][0] = __float_as_uint(sBhi[k1 * SB_STRIDE + n0]);
                bhi[ni][1] = __float_as_uint(sBhi[k2 * SB_STRIDE + n0]);
                blo[ni][0] = __float_as_uint(sBlo[k1 * SB_STRIDE + n0]);
                blo[ni][1] = __float_as_uint(sBlo[k2 * SB_STRIDE + n0]);
            }
            // term-outer ordering: 16 independent acc chains between
            // dependent mmas on the same accumulator.
#pragma unroll
            for (int mi = 0; mi < 4; mi++)
#pragma unroll
                for (int ni = 0; ni < 4; ni++)
                    mma_tf32(acc[mi][ni], alo[mi], bhi[ni]);
#pragma unroll
            for (int mi = 0; mi < 4; mi++)
#pragma unroll
                for (int ni = 0; ni < 4; ni++)
                    mma_tf32(acc[mi][ni], ahi[mi], blo[ni]);
#pragma unroll
            for (int mi = 0; mi < 4; mi++)
#pragma unroll
                for (int ni = 0; ni < 4; ni++)
                    mma_tf32(acc[mi][ni], ahi[mi], bhi[ni]);
        }

        __syncthreads();
        if (has_next) {
            storeS();
            __syncthreads();
        }
    }

    // epilogue
#pragma unroll
    for (int mi = 0; mi < 4; mi++) {
#pragma unroll
        for (int ni = 0; ni < 4; ni++) {
            const int col = colBase + nBase + ni * 8 + 2 * tig;
            if (col >= N) continue;
            float bx = 0.f, by = 0.f;
            if (bias) { bx = __ldg(&bias[col]); by = __ldg(&bias[col + 1]); }
            const int row0 = rowBase + mBase + mi * 16 + g;
            const int row1 = row0 + 8;
            if (row0 < M) {
                float2 v = make_float2(acc[mi][ni][0] + bx, acc[mi][ni][1] + by);
                *(float2*)(C + (size_t)row0 * N + col) = v;
            }
            if (row1 < M) {
                float2 v = make_float2(acc[mi][ni][2] + bx, acc[mi][ni][3] + by);
                *(float2*)(C + (size_t)row1 * N + col) = v;
            }
        }
    }
}

// ============================================================================
// CSR build: histogram -> scan -> scatter
// ============================================================================
__global__ void count_kernel(const int* __restrict__ dst, int* __restrict__ counts, int E)
{
    int e = blockIdx.x * blockDim.x + threadIdx.x;
    if (e < E) atomicAdd(&counts[dst[e]], 1);
}

__global__ void __launch_bounds__(1024)
scan_kernel(const int* __restrict__ counts, int* __restrict__ rowptr, int n)
{
    __shared__ int sm[1024];
    __shared__ int carry_s;
    int tid = threadIdx.x;
    if (tid == 0) carry_s = 0;
    __syncthreads();
    for (int base = 0; base < n; base += 1024) {
        int v = (base + tid < n) ? counts[base + tid] : 0;
        sm[tid] = v;
        __syncthreads();
#pragma unroll
        for (int off = 1; off < 1024; off <<= 1) {
            int t = (tid >= off) ? sm[tid - off] : 0;
            __syncthreads();
            sm[tid] += t;
            __syncthreads();
        }
        int carry = carry_s;
        if (base + tid < n) rowptr[base + tid] = carry + sm[tid] - v;
        __syncthreads();
        if (tid == 1023) carry_s = carry + sm[1023];
        __syncthreads();
    }
    if (tid == 0) rowptr[n] = carry_s;
}

__global__ void scatter_kernel(const int* __restrict__ src, const int* __restrict__ dst,
                               const float* __restrict__ w,
                               const int* __restrict__ rowptr, int* __restrict__ cursor,
                               int* __restrict__ csr_src, float* __restrict__ csr_w, int E)
{
    int e = blockIdx.x * blockDim.x + threadIdx.x;
    if (e >= E) return;
    int d = dst[e];
    int pos = rowptr[d] + atomicAdd(&cursor[d], 1);
    csr_src[pos] = src[e];
    csr_w[pos]   = w[e];
}

// ============================================================================
// Gather SpMM, both branches fused, bias(+relu) fused.
// ============================================================================
__global__ void __launch_bounds__(256)
spmm_csr_dual_kernel(const int* __restrict__ rowptr,
                     const int* __restrict__ csr_src, const float* __restrict__ csr_w,
                     const float* __restrict__ ha, const float* __restrict__ hb,
                     float* __restrict__ oa, float* __restrict__ ob,
                     const float* __restrict__ bias_a, const float* __restrict__ bias_b,
                     int Nn, int do_relu)
{
    int node = blockIdx.x * 4 + (threadIdx.x >> 6);
    int c    = threadIdx.x & 63;
    if (node >= Nn) return;

    const float4* ha4 = (const float4*)ha;
    const float4* hb4 = (const float4*)hb;

    float4 acca = make_float4(0.f, 0.f, 0.f, 0.f);
    float4 accb = make_float4(0.f, 0.f, 0.f, 0.f);

    int beg = __ldg(&rowptr[node]);
    int end = __ldg(&rowptr[node + 1]);
    for (int i = beg; i < end; i++) {
        int   s = __ldg(&csr_src[i]);
        float w = __ldg(&csr_w[i]);
        float4 va = __ldg(&ha4[(size_t)s * 64 + c]);
        float4 vb = __ldg(&hb4[(size_t)s * 64 + c]);
        acca.x = fmaf(w, va.x, acca.x); acca.y = fmaf(w, va.y, acca.y);
        acca.z = fmaf(w, va.z, acca.z); acca.w = fmaf(w, va.w, acca.w);
        accb.x = fmaf(w, vb.x, accb.x); accb.y = fmaf(w, vb.y, accb.y);
        accb.z = fmaf(w, vb.z, accb.z); accb.w = fmaf(w, vb.w, accb.w);
    }

    float4 ba = __ldg(&((const float4*)bias_a)[c]);
    float4 bb = __ldg(&((const float4*)bias_b)[c]);
    acca.x += ba.x; acca.y += ba.y; acca.z += ba.z; acca.w += ba.w;
    accb.x += bb.x; accb.y += bb.y; accb.z += bb.z; accb.w += bb.w;
    if (do_relu) {
        acca.x = fmaxf(acca.x, 0.f); acca.y = fmaxf(acca.y, 0.f);
        acca.z = fmaxf(acca.z, 0.f); acca.w = fmaxf(acca.w, 0.f);
        accb.x = fmaxf(accb.x, 0.f); accb.y = fmaxf(accb.y, 0.f);
        accb.z = fmaxf(accb.z, 0.f); accb.w = fmaxf(accb.w, 0.f);
    }
    ((float4*)oa)[(size_t)node * 64 + c] = acca;
    ((float4*)ob)[(size_t)node * 64 + c] = accb;
}

// ============================================================================
// row-wise log_softmax, one warp per row; strided output
// ============================================================================
template <int L>
__global__ void logsoftmax_kernel(const float* __restrict__ in, float* __restrict__ out,
                                  int nrows, int out_stride)
{
    int row  = blockIdx.x * (blockDim.x >> 5) + (threadIdx.x >> 5);
    int lane = threadIdx.x & 31;
    if (row >= nrows) return;
    const float* r = in + (size_t)row * L;
    float vals[L / 32];
    float m = -3.4e38f;
#pragma unroll
    for (int t = 0; t < L / 32; t++) {
        vals[t] = r[lane + t * 32];
        m = fmaxf(m, vals[t]);
    }
#pragma unroll
    for (int o = 16; o; o >>= 1) m = fmaxf(m, __shfl_xor_sync(0xffffffffu, m, o));
    float s = 0.f;
#pragma unroll
    for (int t = 0; t < L / 32; t++) s += expf(vals[t] - m);
#pragma unroll
    for (int o = 16; o; o >>= 1) s += __shfl_xor_sync(0xffffffffu, s, o);
    float lse = m + logf(s);
    float* wptr = out + (size_t)row * out_stride;
#pragma unroll
    for (int t = 0; t < L / 32; t++) wptr[lane + t * 32] = vals[t] - lse;
}

// ============================================================================
// host side
// ============================================================================
static void sgemm(const float* A, const float* B, const float* bias, float* C,
                  int M, int N, int K)
{
    dim3 grid((N + BN - 1) / BN, (M + BM - 1) / BM);
    gemm_tc_kernel<<<grid, 256, SMEM_WORDS * sizeof(float)>>>(A, B, bias, C, M, N, K);
}

extern "C" void kernel_launch(void* const* d_in, const int* in_sizes, int n_in,
                              void* d_out, int out_size)
{
    const float* x0   = (const float*)d_in[0];
    const float* x1   = (const float*)d_in[1];
    const int*   esrc = (const int*)d_in[2];
    const int*   edst = (const int*)d_in[3];
    const float* ew   = (const float*)d_in[4];
    const float* W1a = (const float*)d_in[5];  const float* b1a = (const float*)d_in[6];
    const float* W2a = (const float*)d_in[7];  const float* b2a = (const float*)d_in[8];
    const float* LWa = (const float*)d_in[9];  const float* Lba = (const float*)d_in[10];
    const float* W1b = (const float*)d_in[11]; const float* b1b = (const float*)d_in[12];
    const float* W2b = (const float*)d_in[13]; const float* b2b = (const float*)d_in[14];
    const float* LWb = (const float*)d_in[15]; const float* Lbb = (const float*)d_in[16];
    const float* LW  = (const float*)d_in[17]; const float* Lb  = (const float*)d_in[18];

    const int Nn = in_sizes[0] / F0DIM;
    const int E  = in_sizes[2];

    static bool attr_done = false;
    if (!attr_done) {
        cudaFuncSetAttribute(gemm_tc_kernel,
                             cudaFuncAttributeMaxDynamicSharedMemorySize,
                             SMEM_WORDS * sizeof(float));
        attr_done = true;
    }

    float *Aa, *Ab, *Ba, *Bb, *CAT;
    cudaGetSymbolAddress((void**)&Aa,  g_Aa);
    cudaGetSymbolAddress((void**)&Ab,  g_Ab);
    cudaGetSymbolAddress((void**)&Ba,  g_Ba);
    cudaGetSymbolAddress((void**)&Bb,  g_Bb);
    cudaGetSymbolAddress((void**)&CAT, g_CAT);

    int *counts, *cursor, *rowptr, *csr_src;
    float *csr_w;
    cudaGetSymbolAddress((void**)&counts,  g_counts);
    cudaGetSymbolAddress((void**)&cursor,  g_cursor);
    cudaGetSymbolAddress((void**)&rowptr,  g_rowptr);
    cudaGetSymbolAddress((void**)&csr_src, g_csr_src);
    cudaGetSymbolAddress((void**)&csr_w,   g_csr_w);

    // ---- build CSR by dst ----
    cudaMemsetAsync(counts, 0, Nn * sizeof(int), 0);
    cudaMemsetAsync(cursor, 0, Nn * sizeof(int), 0);
    count_kernel<<<(E + 255) / 256, 256>>>(edst, counts, E);
    scan_kernel<<<1, 1024>>>(counts, rowptr, Nn);
    scatter_kernel<<<(E + 255) / 256, 256>>>(esrc, edst, ew, rowptr, cursor,
                                             csr_src, csr_w, E);

    const int spmmGrid = (Nn + 3) / 4;

    // ---- layer 1 ----
    sgemm(x0, W1a, nullptr, Aa, Nn, HDIM, F0DIM);
    sgemm(x1, W1b, nullptr, Ab, Nn, HDIM, F0DIM);
    spmm_csr_dual_kernel<<<spmmGrid, 256>>>(rowptr, csr_src, csr_w,
                                            Aa, Ab, Ba, Bb, b1a, b1b, Nn, 1);
    // ---- layer 2 ----
    sgemm(Ba, W2a, nullptr, Aa, Nn, HDIM, HDIM);
    sgemm(Bb, W2b, nullptr, Ab, Nn, HDIM, HDIM);
    spmm_csr_dual_kernel<<<spmmGrid, 256>>>(rowptr, csr_src, csr_w,
                                            Aa, Ab, Ba, Bb, b2a, b2b, Nn, 0);
    // ---- branch heads: linear + log_softmax directly into CAT ----
    sgemm(Ba, LWa, Lba, Aa, Nn, HDIM, HDIM);
    sgemm(Bb, LWb, Lbb, Ab, Nn, HDIM, HDIM);
    logsoftmax_kernel<HDIM><<<(Nn + 7) / 8, 256>>>(Aa, CAT,        Nn, 2 * HDIM);
    logsoftmax_kernel<HDIM><<<(Nn + 7) / 8, 256>>>(Ab, CAT + HDIM, Nn, 2 * HDIM);

    // ---- final: out = log_softmax(CAT @ LW + Lb) ----
    sgemm(CAT, LW, Lb, Aa, Nn, CDIM, 2 * HDIM);
    logsoftmax_kernel<CDIM><<<(Nn + 7) / 8, 256>>>(Aa, (float*)d_out, Nn, CDIM);
}

// round 6
// speedup vs baseline: 1.5712x; 1.1920x over previous
#include <cuda_runtime.h>
#include <cuda_fp16.h>
#include <math.h>
#include <stdint.h>

#define HDIM   256
#define F0DIM  512
#define CDIM   64
#define MAXN   50000
#define MAXE   800000

// -------- static device scratch (no allocations allowed) --------
__device__ float g_Aa[(size_t)MAXN * HDIM];
__device__ float g_Ab[(size_t)MAXN * HDIM];
__device__ float g_Ba[(size_t)MAXN * HDIM];
__device__ float g_Bb[(size_t)MAXN * HDIM];
__device__ float g_CAT[(size_t)MAXN * 2 * HDIM];

__device__ int   g_counts[MAXN];
__device__ int   g_cursor[MAXN];
__device__ int   g_rowptr[MAXN + 1];
__device__ int   g_csr_src[MAXE];
__device__ float g_csr_w[MAXE];

// ============================================================================
// Tensor-core GEMM, mma.sync m16n8k16 fp16 with hi/lo compensation
// (hi*hi + hi*lo + lo*hi; residual ~2^-22 => ~fp32 accuracy).
// Split done once at SMEM store into 4 half2 planes, k-pairs packed in half2.
// 128x128 tile, BK=32, 256 thr (8 warps 2x4), warp tile 64x32.
// ============================================================================
#define BM 128
#define BN 128
#define BKK 32
#define K2ROWS (BKK / 2)                 // 16 half2 k-pair rows
#define SA2 (BM + 8)                     // half2 units per k2-row
#define SB2 (BN + 8)

__device__ __forceinline__ void split_h2(float a, float b, __half2& hi, __half2& lo) {
    __half ha = __float2half_rn(a), hb = __float2half_rn(b);
    float ra = a - __half2float(ha), rb = b - __half2float(hb);
    hi = __halves2half2(ha, hb);
    lo = __halves2half2(__float2half_rn(ra), __float2half_rn(rb));
}

__device__ __forceinline__ void mma_f16(float c[4], const uint32_t a[4], const uint32_t b[2]) {
    asm volatile(
        "mma.sync.aligned.m16n8k16.row.col.f32.f16.f16.f32 "
        "{%0,%1,%2,%3}, {%4,%5,%6,%7}, {%8,%9}, {%0,%1,%2,%3};"
        : "+f"(c[0]), "+f"(c[1]), "+f"(c[2]), "+f"(c[3])
        : "r"(a[0]), "r"(a[1]), "r"(a[2]), "r"(a[3]), "r"(b[0]), "r"(b[1]));
}

__global__ void __launch_bounds__(256)
gemm_tc_kernel(const float* __restrict__ A, const float* __restrict__ B,
               const float* __restrict__ bias, float* __restrict__ C,
               int M, int N, int K)
{
    __shared__ __half2 sAhi[K2ROWS * SA2];
    __shared__ __half2 sAlo[K2ROWS * SA2];
    __shared__ __half2 sBhi[K2ROWS * SB2];
    __shared__ __half2 sBlo[K2ROWS * SB2];

    const int tid  = threadIdx.x;
    const int warp = tid >> 5;
    const int lane = tid & 31;
    const int g    = lane >> 2;
    const int tig  = lane & 3;
    const int mBase = (warp & 1) * 64;
    const int nBase = (warp >> 1) * 32;
    const int rowBase = blockIdx.y * BM;
    const int colBase = blockIdx.x * BN;

    float acc[4][4][4];
#pragma unroll
    for (int i = 0; i < 4; i++)
#pragma unroll
        for (int j = 0; j < 4; j++)
#pragma unroll
            for (int r = 0; r < 4; r++) acc[i][j][r] = 0.f;

    // global-load indexing
    const int ar   = tid >> 1;            // A row 0..127
    const int ak0  = (tid & 1) * 16;      // A k offset (floats)
    const int ak2  = (tid & 1) * 8;       // A k2 offset (pairs)
    const int br2  = (tid >> 4) * 2;      // B k-row pair base 0,2..30
    const int bk2  = tid >> 4;            // B k2 row 0..15
    const int bc0  = (tid & 15) * 8;      // B col base (floats)

    float4 pa[4], pb[4];

    auto loadG = [&](int k0) {
        const int grow = rowBase + ar;
        if (grow < M) {
            const float* ap = A + (size_t)grow * K + k0 + ak0;
#pragma unroll
            for (int j = 0; j < 4; j++) pa[j] = *(const float4*)(ap + j * 4);
        } else {
#pragma unroll
            for (int j = 0; j < 4; j++) pa[j] = make_float4(0.f, 0.f, 0.f, 0.f);
        }
        // B rows br2, br2+1; cols bc0..bc0+7
        const float* bp0 = B + (size_t)(k0 + br2) * N + colBase + bc0;
        const float* bp1 = bp0 + N;
#pragma unroll
        for (int j = 0; j < 2; j++) {
            int gcol = colBase + bc0 + 4 * j;
            bool ok = (gcol < N);
            pb[j]     = ok ? *(const float4*)(bp0 + 4 * j) : make_float4(0.f, 0.f, 0.f, 0.f);
            pb[2 + j] = ok ? *(const float4*)(bp1 + 4 * j) : make_float4(0.f, 0.f, 0.f, 0.f);
        }
    };
    auto storeS = [&]() {
        // A: 4 float4 = 16 consecutive k at row ar -> 8 half2 pairs
#pragma unroll
        for (int j = 0; j < 4; j++) {
            int k2 = ak2 + 2 * j;
            __half2 hi, lo;
            split_h2(pa[j].x, pa[j].y, hi, lo);
            sAhi[k2 * SA2 + ar] = hi;  sAlo[k2 * SA2 + ar] = lo;
            split_h2(pa[j].z, pa[j].w, hi, lo);
            sAhi[(k2 + 1) * SA2 + ar] = hi;  sAlo[(k2 + 1) * SA2 + ar] = lo;
        }
        // B: pair rows (br2, br2+1) across 8 cols -> half2 (k even, k odd)
#pragma unroll
        for (int j = 0; j < 2; j++) {
            const float t[4] = { pb[j].x, pb[j].y, pb[j].z, pb[j].w };
            const float u[4] = { pb[2 + j].x, pb[2 + j].y, pb[2 + j].z, pb[2 + j].w };
#pragma unroll
            for (int c = 0; c < 4; c++) {
                int col = bc0 + 4 * j + c;
                __half2 hi, lo;
                split_h2(t[c], u[c], hi, lo);
                sBhi[bk2 * SB2 + col] = hi;  sBlo[bk2 * SB2 + col] = lo;
            }
        }
    };

    loadG(0);
    storeS();
    __syncthreads();

    const int nIter = K / BKK;
    for (int it = 0; it < nIter; it++) {
        const bool has_next = (it + 1) < nIter;
        if (has_next) loadG((it + 1) * BKK);

#pragma unroll
        for (int ks = 0; ks < 2; ks++) {          // two k16 chunks per BK=32
            const int k2a = ks * 8 + tig;         // k2 rows tig, tig+4
            const int k2b = k2a + 4;

            uint32_t ahi[4][4], alo[4][4];
#pragma unroll
            for (int mi = 0; mi < 4; mi++) {
                const int m0 = mBase + mi * 16 + g;
                ahi[mi][0] = *(const uint32_t*)&sAhi[k2a * SA2 + m0];
                ahi[mi][1] = *(const uint32_t*)&sAhi[k2a * SA2 + m0 + 8];
                ahi[mi][2] = *(const uint32_t*)&sAhi[k2b * SA2 + m0];
                ahi[mi][3] = *(const uint32_t*)&sAhi[k2b * SA2 + m0 + 8];
                alo[mi][0] = *(const uint32_t*)&sAlo[k2a * SA2 + m0];
                alo[mi][1] = *(const uint32_t*)&sAlo[k2a * SA2 + m0 + 8];
                alo[mi][2] = *(const uint32_t*)&sAlo[k2b * SA2 + m0];
                alo[mi][3] = *(const uint32_t*)&sAlo[k2b * SA2 + m0 + 8];
            }
            uint32_t bhi[4][2], blo[4][2];
#pragma unroll
            for (int ni = 0; ni < 4; ni++) {
                const int n0 = nBase + ni * 8 + g;
                bhi[ni][0] = *(const uint32_t*)&sBhi[k2a * SB2 + n0];
                bhi[ni][1] = *(const uint32_t*)&sBhi[k2b * SB2 + n0];
                blo[ni][0] = *(const uint32_t*)&sBlo[k2a * SB2 + n0];
                blo[ni][1] = *(const uint32_t*)&sBlo[k2b * SB2 + n0];
            }
            // term-outer: independent accumulator chains between dependent mmas
#pragma unroll
            for (int mi = 0; mi < 4; mi++)
#pragma unroll
                for (int ni = 0; ni < 4; ni++)
                    mma_f16(acc[mi][ni], alo[mi], bhi[ni]);
#pragma unroll
            for (int mi = 0; mi < 4; mi++)
#pragma unroll
                for (int ni = 0; ni < 4; ni++)
                    mma_f16(acc[mi][ni], ahi[mi], blo[ni]);
#pragma unroll
            for (int mi = 0; mi < 4; mi++)
#pragma unroll
                for (int ni = 0; ni < 4; ni++)
                    mma_f16(acc[mi][ni], ahi[mi], bhi[ni]);
        }

        __syncthreads();
        if (has_next) {
            storeS();
            __syncthreads();
        }
    }

    // epilogue (C frag layout identical to k8 variant)
#pragma unroll
    for (int mi = 0; mi < 4; mi++) {
#pragma unroll
        for (int ni = 0; ni < 4; ni++) {
            const int col = colBase + nBase + ni * 8 + 2 * tig;
            if (col >= N) continue;
            float bx = 0.f, by = 0.f;
            if (bias) { bx = __ldg(&bias[col]); by = __ldg(&bias[col + 1]); }
            const int row0 = rowBase + mBase + mi * 16 + g;
            const int row1 = row0 + 8;
            if (row0 < M) {
                float2 v = make_float2(acc[mi][ni][0] + bx, acc[mi][ni][1] + by);
                *(float2*)(C + (size_t)row0 * N + col) = v;
            }
            if (row1 < M) {
                float2 v = make_float2(acc[mi][ni][2] + bx, acc[mi][ni][3] + by);
                *(float2*)(C + (size_t)row1 * N + col) = v;
            }
        }
    }
}

// ============================================================================
// CSR build: histogram -> scan -> scatter
// ============================================================================
__global__ void count_kernel(const int* __restrict__ dst, int* __restrict__ counts, int E)
{
    int e = blockIdx.x * blockDim.x + threadIdx.x;
    if (e < E) atomicAdd(&counts[dst[e]], 1);
}

__global__ void __launch_bounds__(1024)
scan_kernel(const int* __restrict__ counts, int* __restrict__ rowptr, int n)
{
    __shared__ int sm[1024];
    __shared__ int carry_s;
    int tid = threadIdx.x;
    if (tid == 0) carry_s = 0;
    __syncthreads();
    for (int base = 0; base < n; base += 1024) {
        int v = (base + tid < n) ? counts[base + tid] : 0;
        sm[tid] = v;
        __syncthreads();
#pragma unroll
        for (int off = 1; off < 1024; off <<= 1) {
            int t = (tid >= off) ? sm[tid - off] : 0;
            __syncthreads();
            sm[tid] += t;
            __syncthreads();
        }
        int carry = carry_s;
        if (base + tid < n) rowptr[base + tid] = carry + sm[tid] - v;
        __syncthreads();
        if (tid == 1023) carry_s = carry + sm[1023];
        __syncthreads();
    }
    if (tid == 0) rowptr[n] = carry_s;
}

__global__ void scatter_kernel(const int* __restrict__ src, const int* __restrict__ dst,
                               const float* __restrict__ w,
                               const int* __restrict__ rowptr, int* __restrict__ cursor,
                               int* __restrict__ csr_src, float* __restrict__ csr_w, int E)
{
    int e = blockIdx.x * blockDim.x + threadIdx.x;
    if (e >= E) return;
    int d = dst[e];
    int pos = rowptr[d] + atomicAdd(&cursor[d], 1);
    csr_src[pos] = src[e];
    csr_w[pos]   = w[e];
}

// ============================================================================
// Gather SpMM, both branches fused, bias(+relu) fused.
// ============================================================================
__global__ void __launch_bounds__(256)
spmm_csr_dual_kernel(const int* __restrict__ rowptr,
                     const int* __restrict__ csr_src, const float* __restrict__ csr_w,
                     const float* __restrict__ ha, const float* __restrict__ hb,
                     float* __restrict__ oa, float* __restrict__ ob,
                     const float* __restrict__ bias_a, const float* __restrict__ bias_b,
                     int Nn, int do_relu)
{
    int node = blockIdx.x * 4 + (threadIdx.x >> 6);
    int c    = threadIdx.x & 63;
    if (node >= Nn) return;

    const float4* ha4 = (const float4*)ha;
    const float4* hb4 = (const float4*)hb;

    float4 acca = make_float4(0.f, 0.f, 0.f, 0.f);
    float4 accb = make_float4(0.f, 0.f, 0.f, 0.f);

    int beg = __ldg(&rowptr[node]);
    int end = __ldg(&rowptr[node + 1]);
    for (int i = beg; i < end; i++) {
        int   s = __ldg(&csr_src[i]);
        float w = __ldg(&csr_w[i]);
        float4 va = __ldg(&ha4[(size_t)s * 64 + c]);
        float4 vb = __ldg(&hb4[(size_t)s * 64 + c]);
        acca.x = fmaf(w, va.x, acca.x); acca.y = fmaf(w, va.y, acca.y);
        acca.z = fmaf(w, va.z, acca.z); acca.w = fmaf(w, va.w, acca.w);
        accb.x = fmaf(w, vb.x, accb.x); accb.y = fmaf(w, vb.y, accb.y);
        accb.z = fmaf(w, vb.z, accb.z); accb.w = fmaf(w, vb.w, accb.w);
    }

    float4 ba = __ldg(&((const float4*)bias_a)[c]);
    float4 bb = __ldg(&((const float4*)bias_b)[c]);
    acca.x += ba.x; acca.y += ba.y; acca.z += ba.z; acca.w += ba.w;
    accb.x += bb.x; accb.y += bb.y; accb.z += bb.z; accb.w += bb.w;
    if (do_relu) {
        acca.x = fmaxf(acca.x, 0.f); acca.y = fmaxf(acca.y, 0.f);
        acca.z = fmaxf(acca.z, 0.f); acca.w = fmaxf(acca.w, 0.f);
        accb.x = fmaxf(accb.x, 0.f); accb.y = fmaxf(accb.y, 0.f);
        accb.z = fmaxf(accb.z, 0.f); accb.w = fmaxf(accb.w, 0.f);
    }
    ((float4*)oa)[(size_t)node * 64 + c] = acca;
    ((float4*)ob)[(size_t)node * 64 + c] = accb;
}

// ============================================================================
// row-wise log_softmax, one warp per row; strided output
// ============================================================================
template <int L>
__global__ void logsoftmax_kernel(const float* __restrict__ in, float* __restrict__ out,
                                  int nrows, int out_stride)
{
    int row  = blockIdx.x * (blockDim.x >> 5) + (threadIdx.x >> 5);
    int lane = threadIdx.x & 31;
    if (row >= nrows) return;
    const float* r = in + (size_t)row * L;
    float vals[L / 32];
    float m = -3.4e38f;
#pragma unroll
    for (int t = 0; t < L / 32; t++) {
        vals[t] = r[lane + t * 32];
        m = fmaxf(m, vals[t]);
    }
#pragma unroll
    for (int o = 16; o; o >>= 1) m = fmaxf(m, __shfl_xor_sync(0xffffffffu, m, o));
    float s = 0.f;
#pragma unroll
    for (int t = 0; t < L / 32; t++) s += expf(vals[t] - m);
#pragma unroll
    for (int o = 16; o; o >>= 1) s += __shfl_xor_sync(0xffffffffu, s, o);
    float lse = m + logf(s);
    float* wptr = out + (size_t)row * out_stride;
#pragma unroll
    for (int t = 0; t < L / 32; t++) wptr[lane + t * 32] = vals[t] - lse;
}

// ============================================================================
// host side
// ============================================================================
static void sgemm(const float* A, const float* B, const float* bias, float* C,
                  int M, int N, int K)
{
    dim3 grid((N + BN - 1) / BN, (M + BM - 1) / BM);
    gemm_tc_kernel<<<grid, 256>>>(A, B, bias, C, M, N, K);
}

extern "C" void kernel_launch(void* const* d_in, const int* in_sizes, int n_in,
                              void* d_out, int out_size)
{
    const float* x0   = (const float*)d_in[0];
    const float* x1   = (const float*)d_in[1];
    const int*   esrc = (const int*)d_in[2];
    const int*   edst = (const int*)d_in[3];
    const float* ew   = (const float*)d_in[4];
    const float* W1a = (const float*)d_in[5];  const float* b1a = (const float*)d_in[6];
    const float* W2a = (const float*)d_in[7];  const float* b2a = (const float*)d_in[8];
    const float* LWa = (const float*)d_in[9];  const float* Lba = (const float*)d_in[10];
    const float* W1b = (const float*)d_in[11]; const float* b1b = (const float*)d_in[12];
    const float* W2b = (const float*)d_in[13]; const float* b2b = (const float*)d_in[14];
    const float* LWb = (const float*)d_in[15]; const float* Lbb = (const float*)d_in[16];
    const float* LW  = (const float*)d_in[17]; const float* Lb  = (const float*)d_in[18];

    const int Nn = in_sizes[0] / F0DIM;
    const int E  = in_sizes[2];

    float *Aa, *Ab, *Ba, *Bb, *CAT;
    cudaGetSymbolAddress((void**)&Aa,  g_Aa);
    cudaGetSymbolAddress((void**)&Ab,  g_Ab);
    cudaGetSymbolAddress((void**)&Ba,  g_Ba);
    cudaGetSymbolAddress((void**)&Bb,  g_Bb);
    cudaGetSymbolAddress((void**)&CAT, g_CAT);

    int *counts, *cursor, *rowptr, *csr_src;
    float *csr_w;
    cudaGetSymbolAddress((void**)&counts,  g_counts);
    cudaGetSymbolAddress((void**)&cursor,  g_cursor);
    cudaGetSymbolAddress((void**)&rowptr,  g_rowptr);
    cudaGetSymbolAddress((void**)&csr_src, g_csr_src);
    cudaGetSymbolAddress((void**)&csr_w,   g_csr_w);

    // ---- build CSR by dst ----
    cudaMemsetAsync(counts, 0, Nn * sizeof(int), 0);
    cudaMemsetAsync(cursor, 0, Nn * sizeof(int), 0);
    count_kernel<<<(E + 255) / 256, 256>>>(edst, counts, E);
    scan_kernel<<<1, 1024>>>(counts, rowptr, Nn);
    scatter_kernel<<<(E + 255) / 256, 256>>>(esrc, edst, ew, rowptr, cursor,
                                             csr_src, csr_w, E);

    const int spmmGrid = (Nn + 3) / 4;

    // ---- layer 1 ----
    sgemm(x0, W1a, nullptr, Aa, Nn, HDIM, F0DIM);
    sgemm(x1, W1b, nullptr, Ab, Nn, HDIM, F0DIM);
    spmm_csr_dual_kernel<<<spmmGrid, 256>>>(rowptr, csr_src, csr_w,
                                            Aa, Ab, Ba, Bb, b1a, b1b, Nn, 1);
    // ---- layer 2 ----
    sgemm(Ba, W2a, nullptr, Aa, Nn, HDIM, HDIM);
    sgemm(Bb, W2b, nullptr, Ab, Nn, HDIM, HDIM);
    spmm_csr_dual_kernel<<<spmmGrid, 256>>>(rowptr, csr_src, csr_w,
                                            Aa, Ab, Ba, Bb, b2a, b2b, Nn, 0);
    // ---- branch heads: linear + log_softmax directly into CAT ----
    sgemm(Ba, LWa, Lba, Aa, Nn, HDIM, HDIM);
    sgemm(Bb, LWb, Lbb, Ab, Nn, HDIM, HDIM);
    logsoftmax_kernel<HDIM><<<(Nn + 7) / 8, 256>>>(Aa, CAT,        Nn, 2 * HDIM);
    logsoftmax_kernel<HDIM><<<(Nn + 7) / 8, 256>>>(Ab, CAT + HDIM, Nn, 2 * HDIM);

    // ---- final: out = log_softmax(CAT @ LW + Lb) ----
    sgemm(CAT, LW, Lb, Aa, Nn, CDIM, 2 * HDIM);
    logsoftmax_kernel<CDIM><<<(Nn + 7) / 8, 256>>>(Aa, (float*)d_out, Nn, CDIM);
}

// round 7
// speedup vs baseline: 1.7023x; 1.0835x over previous
#include <cuda_runtime.h>
#include <cuda_fp16.h>
#include <math.h>
#include <stdint.h>

#define HDIM   256
#define F0DIM  512
#define CDIM   64
#define MAXN   50000
#define MAXE   800000

// -------- static device scratch (no allocations allowed) --------
__device__ float g_Aa[(size_t)MAXN * HDIM];
__device__ float g_Ab[(size_t)MAXN * HDIM];

__device__ __align__(256) __half g_X0hi[(size_t)MAXN * F0DIM];
__device__ __align__(256) __half g_X0lo[(size_t)MAXN * F0DIM];
__device__ __align__(256) __half g_X1hi[(size_t)MAXN * F0DIM];
__device__ __align__(256) __half g_X1lo[(size_t)MAXN * F0DIM];
__device__ __align__(256) __half g_Hahi[(size_t)MAXN * HDIM];
__device__ __align__(256) __half g_Halo[(size_t)MAXN * HDIM];
__device__ __align__(256) __half g_Hbhi[(size_t)MAXN * HDIM];
__device__ __align__(256) __half g_Hblo[(size_t)MAXN * HDIM];
__device__ __align__(256) __half g_CAThi[(size_t)MAXN * 2 * HDIM];
__device__ __align__(256) __half g_CATlo[(size_t)MAXN * 2 * HDIM];
__device__ __align__(256) __half g_Whi[557056];
__device__ __align__(256) __half g_Wlo[557056];

__device__ int   g_counts[MAXN];
__device__ int   g_cursor[MAXN];
__device__ int   g_rowptr[MAXN + 1];
__device__ int   g_csr_src[MAXE];
__device__ float g_csr_w[MAXE];

// weight plane offsets
#define OFF_W1a 0
#define OFF_W2a 131072
#define OFF_LWa 196608
#define OFF_W1b 262144
#define OFF_W2b 393216
#define OFF_LWb 458752
#define OFF_LW  524288

// ============================================================================
// fp32 -> (hi, lo) half planes, 4 elems/thread
// ============================================================================
__global__ void split_kernel(const float* __restrict__ in,
                             __half* __restrict__ hi, __half* __restrict__ lo, int n4)
{
    int i = blockIdx.x * blockDim.x + threadIdx.x;
    if (i >= n4) return;
    float4 v = __ldg(((const float4*)in) + i);
    float f[4] = { v.x, v.y, v.z, v.w };
    __half h[4], l[4];
#pragma unroll
    for (int j = 0; j < 4; j++) {
        h[j] = __float2half_rn(f[j]);
        l[j] = __float2half_rn(f[j] - __half2float(h[j]));
    }
    *(uint2*)(hi + 4 * (size_t)i) = *(uint2*)h;
    *(uint2*)(lo + 4 * (size_t)i) = *(uint2*)l;
}

// ============================================================================
// fp16 tensor-core GEMM with hi/lo compensated inputs (pre-split planes).
// C = A @ B (+bias), fp32 out. 128x128 tile, BK=32, 256 thr (8 warps 2x4),
// double-buffered SMEM, one __syncthreads per iter.
// SMEM planes [k2][m]/[k2][n] of half2 (k-pairs), stride 136: conflict-free.
// ============================================================================
#define BM 128
#define BN 128
#define BKK 32
#define NK2 16
#define SA2 136
#define SB2 136
#define APLANE (NK2 * SA2)
#define BPLANE (NK2 * SB2)
#define BUF_H2 (2 * APLANE + 2 * BPLANE)
#define SMEM_BYTES (2 * BUF_H2 * 4)

__device__ __forceinline__ void mma_f16(float c[4], const uint32_t a[4], const uint32_t b[2]) {
    asm volatile(
        "mma.sync.aligned.m16n8k16.row.col.f32.f16.f16.f32 "
        "{%0,%1,%2,%3}, {%4,%5,%6,%7}, {%8,%9}, {%0,%1,%2,%3};"
        : "+f"(c[0]), "+f"(c[1]), "+f"(c[2]), "+f"(c[3])
        : "r"(a[0]), "r"(a[1]), "r"(a[2]), "r"(a[3]), "r"(b[0]), "r"(b[1]));
}

__global__ void __launch_bounds__(256)
hgemm_kernel(const __half* __restrict__ Ahi, const __half* __restrict__ Alo,
             const __half* __restrict__ Bhi, const __half* __restrict__ Blo,
             const float* __restrict__ bias, float* __restrict__ C,
             int M, int N, int K)
{
    extern __shared__ __half2 sm[];

    const int tid  = threadIdx.x;
    const int warp = tid >> 5;
    const int lane = tid & 31;
    const int g    = lane >> 2;
    const int tig  = lane & 3;
    const int mBase = (warp & 1) * 64;
    const int nBase = (warp >> 1) * 32;
    const int rowBase = blockIdx.y * BM;
    const int colBase = blockIdx.x * BN;

    float acc[4][4][4];
#pragma unroll
    for (int i = 0; i < 4; i++)
#pragma unroll
        for (int j = 0; j < 4; j++)
#pragma unroll
            for (int r = 0; r < 4; r++) acc[i][j][r] = 0.f;

    // A-load: thread -> row (tid&127), k-half (tid>>7)
    const int ar   = tid & 127;
    const int ak2  = (tid >> 7) * 8;     // k2 offset 0/8
    const int aKh  = ak2 * 2;            // halves offset 0/16
    // B-load: warp owns k2 rows {warp, warp+8}; lane -> cols {2l, 2l+64}
    const int bcol0 = 2 * lane;

    uint4    pa[4];     // A: [hi0,hi1,lo0,lo1], 8 halves each
    uint32_t pbr[16];   // B: [plane][k2sel][row parity][chunk]

    auto loadG = [&](int k0) {
        const int grow = rowBase + ar;
        if (grow < M) {
            const __half* pH = Ahi + (size_t)grow * K + k0 + aKh;
            const __half* pL = Alo + (size_t)grow * K + k0 + aKh;
            pa[0] = *(const uint4*)pH;       pa[1] = *(const uint4*)(pH + 8);
            pa[2] = *(const uint4*)pL;       pa[3] = *(const uint4*)(pL + 8);
        } else {
            uint4 z = make_uint4(0u, 0u, 0u, 0u);
            pa[0] = z; pa[1] = z; pa[2] = z; pa[3] = z;
        }
#pragma unroll
        for (int s = 0; s < 2; s++) {
            const int k2 = warp + 8 * s;
            const int kk = k0 + 2 * k2;
#pragma unroll
            for (int c = 0; c < 2; c++) {
                const int col = colBase + bcol0 + 64 * c;
                const bool ok = (col < N);
                const __half* q = Bhi + (size_t)kk * N + col;
                const __half* r = Blo + (size_t)kk * N + col;
                pbr[((0 * 2 + s) * 2 + 0) * 2 + c] = ok ? *(const uint32_t*)q       : 0u;
                pbr[((0 * 2 + s) * 2 + 1) * 2 + c] = ok ? *(const uint32_t*)(q + N) : 0u;
                pbr[((1 * 2 + s) * 2 + 0) * 2 + c] = ok ? *(const uint32_t*)r       : 0u;
                pbr[((1 * 2 + s) * 2 + 1) * 2 + c] = ok ? *(const uint32_t*)(r + N) : 0u;
            }
        }
    };

    auto storeS = [&](int buf) {
        __half2* sA_hi = sm + (size_t)buf * BUF_H2;
        __half2* sA_lo = sA_hi + APLANE;
        __half2* sB_hi = sA_lo + APLANE;
        __half2* sB_lo = sB_hi + BPLANE;
#pragma unroll
        for (int pl = 0; pl < 2; pl++) {
            __half2* dst = pl ? sA_lo : sA_hi;
#pragma unroll
            for (int j = 0; j < 2; j++) {
                uint4 v = pa[pl * 2 + j];
                const uint32_t u[4] = { v.x, v.y, v.z, v.w };
#pragma unroll
                for (int q = 0; q < 4; q++)
                    dst[(ak2 + j * 4 + q) * SA2 + ar] = *(const __half2*)&u[q];
            }
        }
#pragma unroll
        for (int pl = 0; pl < 2; pl++) {
            __half2* dst = pl ? sB_lo : sB_hi;
#pragma unroll
            for (int s = 0; s < 2; s++) {
                const int k2 = warp + 8 * s;
#pragma unroll
                for (int c = 0; c < 2; c++) {
                    uint32_t r0 = pbr[((pl * 2 + s) * 2 + 0) * 2 + c];
                    uint32_t r1 = pbr[((pl * 2 + s) * 2 + 1) * 2 + c];
                    uint2 st = make_uint2(__byte_perm(r0, r1, 0x5410),
                                          __byte_perm(r0, r1, 0x7632));
                    *(uint2*)&dst[k2 * SB2 + bcol0 + 64 * c] = st;
                }
            }
        }
    };

    const int nIter = K / BKK;
    loadG(0);
    storeS(0);
    __syncthreads();
    if (nIter > 1) loadG(BKK);

    for (int it = 0; it < nIter; it++) {
        const __half2* sA_hi = sm + (size_t)(it & 1) * BUF_H2;
        const __half2* sA_lo = sA_hi + APLANE;
        const __half2* sB_hi = sA_lo + APLANE;
        const __half2* sB_lo = sB_hi + BPLANE;

#pragma unroll
        for (int ks = 0; ks < 2; ks++) {
            const int k2a = ks * 8 + tig;
            const int k2b = k2a + 4;

            uint32_t ahi[4][4], alo[4][4];
#pragma unroll
            for (int mi = 0; mi < 4; mi++) {
                const int m0 = mBase + mi * 16 + g;
                ahi[mi][0] = *(const uint32_t*)&sA_hi[k2a * SA2 + m0];
                ahi[mi][1] = *(const uint32_t*)&sA_hi[k2a * SA2 + m0 + 8];
                ahi[mi][2] = *(const uint32_t*)&sA_hi[k2b * SA2 + m0];
                ahi[mi][3] = *(const uint32_t*)&sA_hi[k2b * SA2 + m0 + 8];
                alo[mi][0] = *(const uint32_t*)&sA_lo[k2a * SA2 + m0];
                alo[mi][1] = *(const uint32_t*)&sA_lo[k2a * SA2 + m0 + 8];
                alo[mi][2] = *(const uint32_t*)&sA_lo[k2b * SA2 + m0];
                alo[mi][3] = *(const uint32_t*)&sA_lo[k2b * SA2 + m0 + 8];
            }
            uint32_t bhi[4][2], blo[4][2];
#pragma unroll
            for (int ni = 0; ni < 4; ni++) {
                const int n0 = nBase + ni * 8 + g;
                bhi[ni][0] = *(const uint32_t*)&sB_hi[k2a * SB2 + n0];
                bhi[ni][1] = *(const uint32_t*)&sB_hi[k2b * SB2 + n0];
                blo[ni][0] = *(const uint32_t*)&sB_lo[k2a * SB2 + n0];
                blo[ni][1] = *(const uint32_t*)&sB_lo[k2b * SB2 + n0];
            }
#pragma unroll
            for (int mi = 0; mi < 4; mi++)
#pragma unroll
                for (int ni = 0; ni < 4; ni++)
                    mma_f16(acc[mi][ni], alo[mi], bhi[ni]);
#pragma unroll
            for (int mi = 0; mi < 4; mi++)
#pragma unroll
                for (int ni = 0; ni < 4; ni++)
                    mma_f16(acc[mi][ni], ahi[mi], blo[ni]);
#pragma unroll
            for (int mi = 0; mi < 4; mi++)
#pragma unroll
                for (int ni = 0; ni < 4; ni++)
                    mma_f16(acc[mi][ni], ahi[mi], bhi[ni]);
        }

        if (it + 1 < nIter) storeS((it + 1) & 1);
        __syncthreads();
        if (it + 2 < nIter) loadG((it + 2) * BKK);
    }

    // epilogue
#pragma unroll
    for (int mi = 0; mi < 4; mi++) {
#pragma unroll
        for (int ni = 0; ni < 4; ni++) {
            const int col = colBase + nBase + ni * 8 + 2 * tig;
            if (col >= N) continue;
            float bx = 0.f, by = 0.f;
            if (bias) { bx = __ldg(&bias[col]); by = __ldg(&bias[col + 1]); }
            const int row0 = rowBase + mBase + mi * 16 + g;
            const int row1 = row0 + 8;
            if (row0 < M) {
                float2 v = make_float2(acc[mi][ni][0] + bx, acc[mi][ni][1] + by);
                *(float2*)(C + (size_t)row0 * N + col) = v;
            }
            if (row1 < M) {
                float2 v = make_float2(acc[mi][ni][2] + bx, acc[mi][ni][3] + by);
                *(float2*)(C + (size_t)row1 * N + col) = v;
            }
        }
    }
}

// ============================================================================
// CSR build: histogram -> scan -> scatter
// ============================================================================
__global__ void count_kernel(const int* __restrict__ dst, int* __restrict__ counts, int E)
{
    int e = blockIdx.x * blockDim.x + threadIdx.x;
    if (e < E) atomicAdd(&counts[dst[e]], 1);
}

__global__ void __launch_bounds__(1024)
scan_kernel(const int* __restrict__ counts, int* __restrict__ rowptr, int n)
{
    __shared__ int sm[1024];
    __shared__ int carry_s;
    int tid = threadIdx.x;
    if (tid == 0) carry_s = 0;
    __syncthreads();
    for (int base = 0; base < n; base += 1024) {
        int v = (base + tid < n) ? counts[base + tid] : 0;
        sm[tid] = v;
        __syncthreads();
#pragma unroll
        for (int off = 1; off < 1024; off <<= 1) {
            int t = (tid >= off) ? sm[tid - off] : 0;
            __syncthreads();
            sm[tid] += t;
            __syncthreads();
        }
        int carry = carry_s;
        if (base + tid < n) rowptr[base + tid] = carry + sm[tid] - v;
        __syncthreads();
        if (tid == 1023) carry_s = carry + sm[1023];
        __syncthreads();
    }
    if (tid == 0) rowptr[n] = carry_s;
}

__global__ void scatter_kernel(const int* __restrict__ src, const int* __restrict__ dst,
                               const float* __restrict__ w,
                               const int* __restrict__ rowptr, int* __restrict__ cursor,
                               int* __restrict__ csr_src, float* __restrict__ csr_w, int E)
{
    int e = blockIdx.x * blockDim.x + threadIdx.x;
    if (e >= E) return;
    int d = dst[e];
    int pos = rowptr[d] + atomicAdd(&cursor[d], 1);
    csr_src[pos] = src[e];
    csr_w[pos]   = w[e];
}

// ============================================================================
// Gather SpMM, both branches fused, bias(+relu) fused, emits hi/lo half planes
// ============================================================================
__global__ void __launch_bounds__(256)
spmm_csr_dual_kernel(const int* __restrict__ rowptr,
                     const int* __restrict__ csr_src, const float* __restrict__ csr_w,
                     const float* __restrict__ ha, const float* __restrict__ hb,
                     __half* __restrict__ oa_hi, __half* __restrict__ oa_lo,
                     __half* __restrict__ ob_hi, __half* __restrict__ ob_lo,
                     const float* __restrict__ bias_a, const float* __restrict__ bias_b,
                     int Nn, int do_relu)
{
    int node = blockIdx.x * 4 + (threadIdx.x >> 6);
    int c    = threadIdx.x & 63;
    if (node >= Nn) return;

    const float4* ha4 = (const float4*)ha;
    const float4* hb4 = (const float4*)hb;

    float4 acca = make_float4(0.f, 0.f, 0.f, 0.f);
    float4 accb = make_float4(0.f, 0.f, 0.f, 0.f);

    int beg = __ldg(&rowptr[node]);
    int end = __ldg(&rowptr[node + 1]);
    for (int i = beg; i < end; i++) {
        int   s = __ldg(&csr_src[i]);
        float w = __ldg(&csr_w[i]);
        float4 va = __ldg(&ha4[(size_t)s * 64 + c]);
        float4 vb = __ldg(&hb4[(size_t)s * 64 + c]);
        acca.x = fmaf(w, va.x, acca.x); acca.y = fmaf(w, va.y, acca.y);
        acca.z = fmaf(w, va.z, acca.z); acca.w = fmaf(w, va.w, acca.w);
        accb.x = fmaf(w, vb.x, accb.x); accb.y = fmaf(w, vb.y, accb.y);
        accb.z = fmaf(w, vb.z, accb.z); accb.w = fmaf(w, vb.w, accb.w);
    }

    float4 ba = __ldg(&((const float4*)bias_a)[c]);
    float4 bb = __ldg(&((const float4*)bias_b)[c]);
    acca.x += ba.x; acca.y += ba.y; acca.z += ba.z; acca.w += ba.w;
    accb.x += bb.x; accb.y += bb.y; accb.z += bb.z; accb.w += bb.w;
    if (do_relu) {
        acca.x = fmaxf(acca.x, 0.f); acca.y = fmaxf(acca.y, 0.f);
        acca.z = fmaxf(acca.z, 0.f); acca.w = fmaxf(acca.w, 0.f);
        accb.x = fmaxf(accb.x, 0.f); accb.y = fmaxf(accb.y, 0.f);
        accb.z = fmaxf(accb.z, 0.f); accb.w = fmaxf(accb.w, 0.f);
    }

    const size_t off = (size_t)node * HDIM + 4 * c;
    float fa[4] = { acca.x, acca.y, acca.z, acca.w };
    float fb[4] = { accb.x, accb.y, accb.z, accb.w };
    __half hah[4], hal[4], hbh[4], hbl[4];
#pragma unroll
    for (int j = 0; j < 4; j++) {
        hah[j] = __float2half_rn(fa[j]);
        hal[j] = __float2half_rn(fa[j] - __half2float(hah[j]));
        hbh[j] = __float2half_rn(fb[j]);
        hbl[j] = __float2half_rn(fb[j] - __half2float(hbh[j]));
    }
    *(uint2*)(oa_hi + off) = *(uint2*)hah;
    *(uint2*)(oa_lo + off) = *(uint2*)hal;
    *(uint2*)(ob_hi + off) = *(uint2*)hbh;
    *(uint2*)(ob_lo + off) = *(uint2*)hbl;
}

// ============================================================================
// log_softmax variants (one warp per row)
// ============================================================================
__global__ void logsoftmax_split_kernel(const float* __restrict__ in,
                                        __half* __restrict__ out_hi,
                                        __half* __restrict__ out_lo,
                                        int nrows, int out_stride)
{
    const int L = HDIM;
    int row  = blockIdx.x * (blockDim.x >> 5) + (threadIdx.x >> 5);
    int lane = threadIdx.x & 31;
    if (row >= nrows) return;
    const float* r = in + (size_t)row * L;
    float vals[L / 32];
    float m = -3.4e38f;
#pragma unroll
    for (int t = 0; t < L / 32; t++) {
        vals[t] = r[lane + t * 32];
        m = fmaxf(m, vals[t]);
    }
#pragma unroll
    for (int o = 16; o; o >>= 1) m = fmaxf(m, __shfl_xor_sync(0xffffffffu, m, o));
    float s = 0.f;
#pragma unroll
    for (int t = 0; t < L / 32; t++) s += expf(vals[t] - m);
#pragma unroll
    for (int o = 16; o; o >>= 1) s += __shfl_xor_sync(0xffffffffu, s, o);
    float lse = m + logf(s);
    size_t base = (size_t)row * out_stride;
#pragma unroll
    for (int t = 0; t < L / 32; t++) {
        float v = vals[t] - lse;
        __half h = __float2half_rn(v);
        out_hi[base + lane + t * 32] = h;
        out_lo[base + lane + t * 32] = __float2half_rn(v - __half2float(h));
    }
}

template <int L>
__global__ void logsoftmax_kernel(const float* __restrict__ in, float* __restrict__ out,
                                  int nrows, int out_stride)
{
    int row  = blockIdx.x * (blockDim.x >> 5) + (threadIdx.x >> 5);
    int lane = threadIdx.x & 31;
    if (row >= nrows) return;
    const float* r = in + (size_t)row * L;
    float vals[L / 32];
    float m = -3.4e38f;
#pragma unroll
    for (int t = 0; t < L / 32; t++) {
        vals[t] = r[lane + t * 32];
        m = fmaxf(m, vals[t]);
    }
#pragma unroll
    for (int o = 16; o; o >>= 1) m = fmaxf(m, __shfl_xor_sync(0xffffffffu, m, o));
    float s = 0.f;
#pragma unroll
    for (int t = 0; t < L / 32; t++) s += expf(vals[t] - m);
#pragma unroll
    for (int o = 16; o; o >>= 1) s += __shfl_xor_sync(0xffffffffu, s, o);
    float lse = m + logf(s);
    float* wptr = out + (size_t)row * out_stride;
#pragma unroll
    for (int t = 0; t < L / 32; t++) wptr[lane + t * 32] = vals[t] - lse;
}

// ============================================================================
// host side
// ============================================================================
static void hgemm(const __half* Ahi, const __half* Alo,
                  const __half* Bhi, const __half* Blo,
                  const float* bias, float* C, int M, int N, int K)
{
    dim3 grid((N + BN - 1) / BN, (M + BM - 1) / BM);
    hgemm_kernel<<<grid, 256, SMEM_BYTES>>>(Ahi, Alo, Bhi, Blo, bias, C, M, N, K);
}

static void split(const float* in, __half* hi, __half* lo, int n)
{
    int n4 = n / 4;
    split_kernel<<<(n4 + 255) / 256, 256>>>(in, hi, lo, n4);
}

extern "C" void kernel_launch(void* const* d_in, const int* in_sizes, int n_in,
                              void* d_out, int out_size)
{
    const float* x0   = (const float*)d_in[0];
    const float* x1   = (const float*)d_in[1];
    const int*   esrc = (const int*)d_in[2];
    const int*   edst = (const int*)d_in[3];
    const float* ew   = (const float*)d_in[4];
    const float* W1a = (const float*)d_in[5];  const float* b1a = (const float*)d_in[6];
    const float* W2a = (const float*)d_in[7];  const float* b2a = (const float*)d_in[8];
    const float* LWa = (const float*)d_in[9];  const float* Lba = (const float*)d_in[10];
    const float* W1b = (const float*)d_in[11]; const float* b1b = (const float*)d_in[12];
    const float* W2b = (const float*)d_in[13]; const float* b2b = (const float*)d_in[14];
    const float* LWb = (const float*)d_in[15]; const float* Lbb = (const float*)d_in[16];
    const float* LW  = (const float*)d_in[17]; const float* Lb  = (const float*)d_in[18];

    const int Nn = in_sizes[0] / F0DIM;
    const int E  = in_sizes[2];

    cudaFuncSetAttribute(hgemm_kernel,
                         cudaFuncAttributeMaxDynamicSharedMemorySize, SMEM_BYTES);

    float *Aa, *Ab;
    cudaGetSymbolAddress((void**)&Aa, g_Aa);
    cudaGetSymbolAddress((void**)&Ab, g_Ab);
    __half *X0hi, *X0lo, *X1hi, *X1lo, *Hahi, *Halo, *Hbhi, *Hblo, *CAThi, *CATlo, *Whi, *Wlo;
    cudaGetSymbolAddress((void**)&X0hi, g_X0hi);  cudaGetSymbolAddress((void**)&X0lo, g_X0lo);
    cudaGetSymbolAddress((void**)&X1hi, g_X1hi);  cudaGetSymbolAddress((void**)&X1lo, g_X1lo);
    cudaGetSymbolAddress((void**)&Hahi, g_Hahi);  cudaGetSymbolAddress((void**)&Halo, g_Halo);
    cudaGetSymbolAddress((void**)&Hbhi, g_Hbhi);  cudaGetSymbolAddress((void**)&Hblo, g_Hblo);
    cudaGetSymbolAddress((void**)&CAThi, g_CAThi); cudaGetSymbolAddress((void**)&CATlo, g_CATlo);
    cudaGetSymbolAddress((void**)&Whi, g_Whi);    cudaGetSymbolAddress((void**)&Wlo, g_Wlo);

    int *counts, *cursor, *rowptr, *csr_src;
    float *csr_w;
    cudaGetSymbolAddress((void**)&counts,  g_counts);
    cudaGetSymbolAddress((void**)&cursor,  g_cursor);
    cudaGetSymbolAddress((void**)&rowptr,  g_rowptr);
    cudaGetSymbolAddress((void**)&csr_src, g_csr_src);
    cudaGetSymbolAddress((void**)&csr_w,   g_csr_w);

    // ---- split inputs & weights to half planes ----
    split(x0, X0hi, X0lo, Nn * F0DIM);
    split(x1, X1hi, X1lo, Nn * F0DIM);
    split(W1a, Whi + OFF_W1a, Wlo + OFF_W1a, F0DIM * HDIM);
    split(W2a, Whi + OFF_W2a, Wlo + OFF_W2a, HDIM * HDIM);
    split(LWa, Whi + OFF_LWa, Wlo + OFF_LWa, HDIM * HDIM);
    split(W1b, Whi + OFF_W1b, Wlo + OFF_W1b, F0DIM * HDIM);
    split(W2b, Whi + OFF_W2b, Wlo + OFF_W2b, HDIM * HDIM);
    split(LWb, Whi + OFF_LWb, Wlo + OFF_LWb, HDIM * HDIM);
    split(LW,  Whi + OFF_LW,  Wlo + OFF_LW,  2 * HDIM * CDIM);

    // ---- build CSR by dst ----
    cudaMemsetAsync(counts, 0, Nn * sizeof(int), 0);
    cudaMemsetAsync(cursor, 0, Nn * sizeof(int), 0);
    count_kernel<<<(E + 255) / 256, 256>>>(edst, counts, E);
    scan_kernel<<<1, 1024>>>(counts, rowptr, Nn);
    scatter_kernel<<<(E + 255) / 256, 256>>>(esrc, edst, ew, rowptr, cursor,
                                             csr_src, csr_w, E);

    const int spmmGrid = (Nn + 3) / 4;

    // ---- layer 1 ----
    hgemm(X0hi, X0lo, Whi + OFF_W1a, Wlo + OFF_W1a, nullptr, Aa, Nn, HDIM, F0DIM);
    hgemm(X1hi, X1lo, Whi + OFF_W1b, Wlo + OFF_W1b, nullptr, Ab, Nn, HDIM, F0DIM);
    spmm_csr_dual_kernel<<<spmmGrid, 256>>>(rowptr, csr_src, csr_w, Aa, Ab,
                                            Hahi, Halo, Hbhi, Hblo, b1a, b1b, Nn, 1);
    // ---- layer 2 ----
    hgemm(Hahi, Halo, Whi + OFF_W2a, Wlo + OFF_W2a, nullptr, Aa, Nn, HDIM, HDIM);
    hgemm(Hbhi, Hblo, Whi + OFF_W2b, Wlo + OFF_W2b, nullptr, Ab, Nn, HDIM, HDIM);
    spmm_csr_dual_kernel<<<spmmGrid, 256>>>(rowptr, csr_src, csr_w, Aa, Ab,
                                            Hahi, Halo, Hbhi, Hblo, b2a, b2b, Nn, 0);
    // ---- branch heads: linear + log_softmax into CAT planes ----
    hgemm(Hahi, Halo, Whi + OFF_LWa, Wlo + OFF_LWa, Lba, Aa, Nn, HDIM, HDIM);
    hgemm(Hbhi, Hblo, Whi + OFF_LWb, Wlo + OFF_LWb, Lbb, Ab, Nn, HDIM, HDIM);
    logsoftmax_split_kernel<<<(Nn + 7) / 8, 256>>>(Aa, CAThi,        CATlo,        Nn, 2 * HDIM);
    logsoftmax_split_kernel<<<(Nn + 7) / 8, 256>>>(Ab, CAThi + HDIM, CATlo + HDIM, Nn, 2 * HDIM);

    // ---- final: out = log_softmax(CAT @ LW + Lb) ----
    hgemm(CAThi, CATlo, Whi + OFF_LW, Wlo + OFF_LW, Lb, Aa, Nn, CDIM, 2 * HDIM);
    logsoftmax_kernel<CDIM><<<(Nn + 7) / 8, 256>>>(Aa, (float*)d_out, Nn, CDIM);
}